// round 15
// baseline (speedup 1.0000x reference)
#include <cuda_runtime.h>
#include <math.h>

#define KU 128      // users (K)
#define MD 1024     // M
#define NU 128      // N (== KU)
#define KT 8        // k rows per block tile
#define MCH 32      // m rows per block chunk
#define NKT (KU / KT)    // 16
#define NMC (MD / MCH)   // 32
#define PG 4             // p-groups in k3 phase 1
static __device__ __constant__ float N0F = 1e-11f;  // 10^(-80/10)/1000

// Scratch (static __device__ — no allocation)
__device__ float d_gp_re[NMC * KU * NU];   // per-m-chunk partials of g (2 MB)
__device__ float d_gp_im[NMC * KU * NU];
__device__ float d_gs_re[PG * KU * NU];    // k3 phase-1 compact sums (256 KB)
__device__ float d_gs_im[PG * KU * NU];
__device__ float d_R[KU];
__device__ unsigned int d_kctr[KU];        // per-k finisher counters
__device__ unsigned int d_ctr;             // global finisher counter

__device__ __forceinline__ float dot4(float4 a, float4 b) {
    return fmaf(a.x, b.x, fmaf(a.y, b.y, fmaf(a.z, b.z, a.w * b.w)));
}

// ---------------------------------------------------------------------------
// k12 (UNCHANGED from best-measured R14): stage A = 8-lanes-per-row /
// 4-rows-per-group, double-buffered (next group's 16 LDG.128 issued before the
// current group's consume). v hoisted to registers. stage B contracts the h
// tile against W[m0:m0+32,:] (L2) -> g partials.
// grid (32 mc, 16 kt) = 512 blocks x 256 threads, 2 blocks/SM.
// ---------------------------------------------------------------------------
__global__ __launch_bounds__(256, 2) void k12_fused(
    const float* __restrict__ Wv,
    const float* __restrict__ Ar,
    const float* __restrict__ Ai,
    const float* __restrict__ hdr,
    const float* __restrict__ hdi)
{
    __shared__ float vs[256];         // v_re | v_im
    __shared__ float hsrt[MCH * 8];   // h_re transposed [m][kk]
    __shared__ float hsit[MCH * 8];   // h_im transposed [m][kk]

    const int tid  = threadIdx.x;
    const int lane = tid & 31;
    const int warp = tid >> 5;        // 0..7 == kk
    const int c    = lane & 7;        // position within 8-lane row group
    const int sub  = lane >> 3;       // which of the 4 rows

    const int mc = blockIdx.x;        // 0..31
    const int kt = blockIdx.y;        // 0..15
    const int k0 = kt * KT;
    const int m0 = mc * MCH;

    vs[tid] = Wv[tid];                // 256 floats of v
    __syncthreads();

    // ---- stage A ----
    {
        const int kk = warp;
        const size_t rowbase = (size_t)(k0 + kk) * MD + m0;
        const float4* v4r = reinterpret_cast<const float4*>(vs);
        const float4* v4i = reinterpret_cast<const float4*>(vs + 128);

        const float4 vr0 = v4r[c],      vr1 = v4r[c + 8];
        const float4 vr2 = v4r[c + 16], vr3 = v4r[c + 24];
        const float4 vi0 = v4i[c],      vi1 = v4i[c + 8];
        const float4 vi2 = v4i[c + 16], vi3 = v4i[c + 24];

        const float4* a4 = reinterpret_cast<const float4*>(Ar + (rowbase + sub) * NU);
        const float4* b4 = reinterpret_cast<const float4*>(Ai + (rowbase + sub) * NU);
        float4 a0 = a4[c], a1 = a4[c + 8], a2 = a4[c + 16], a3 = a4[c + 24];
        float4 b0 = b4[c], b1 = b4[c + 8], b2 = b4[c + 16], b3 = b4[c + 24];

#pragma unroll
        for (int it = 0; it < 8; ++it) {
            float4 na0, na1, na2, na3, nb0, nb1, nb2, nb3;
            if (it < 7) {
                const int mn = (it + 1) * 4 + sub;
                const float4* an = reinterpret_cast<const float4*>(Ar + (rowbase + mn) * NU);
                const float4* bn = reinterpret_cast<const float4*>(Ai + (rowbase + mn) * NU);
                na0 = an[c]; na1 = an[c + 8]; na2 = an[c + 16]; na3 = an[c + 24];
                nb0 = bn[c]; nb1 = bn[c + 8]; nb2 = bn[c + 16]; nb3 = bn[c + 24];
            }

            float sre = (dot4(a0, vr0) + dot4(a1, vr1)) + (dot4(a2, vr2) + dot4(a3, vr3))
                      - (dot4(b0, vi0) + dot4(b1, vi1)) - (dot4(b2, vi2) + dot4(b3, vi3));
            float sim = (dot4(b0, vr0) + dot4(b1, vr1)) + (dot4(b2, vr2) + dot4(b3, vr3))
                      + (dot4(a0, vi0) + dot4(a1, vi1)) + (dot4(a2, vi2) + dot4(a3, vi3));

#pragma unroll
            for (int off = 4; off; off >>= 1) {
                sre += __shfl_xor_sync(0xffffffffu, sre, off);
                sim += __shfl_xor_sync(0xffffffffu, sim, off);
            }
            const int m = it * 4 + sub;
            if (c == 0) {
                const size_t row = rowbase + m;
                hsrt[m * 8 + kk] = hdr[row] + sre;
                hsit[m * 8 + kk] = hdi[row] + sim;
            }

            if (it < 7) {
                a0 = na0; a1 = na1; a2 = na2; a3 = na3;
                b0 = nb0; b1 = nb1; b2 = nb2; b3 = nb3;
            }
        }
    }
    __syncthreads();

    // ---- stage B ----
    const int n = tid & 127;          // output column
    const int g = tid >> 7;           // kk group: g*4 .. g*4+3
    {
        float are[4] = {0.f, 0.f, 0.f, 0.f};
        float aim[4] = {0.f, 0.f, 0.f, 0.f};
        const float* Wb = Wv + (size_t)(1 + m0) * 256;   // W rows m0.., stride 256

#pragma unroll 4
        for (int m = 0; m < MCH; m++) {
            const float wre = __ldg(Wb + m * 256 + n);
            const float wim = __ldg(Wb + m * 256 + 128 + n);
            const float4 hre = *reinterpret_cast<const float4*>(&hsrt[m * 8 + g * 4]);
            const float4 him = *reinterpret_cast<const float4*>(&hsit[m * 8 + g * 4]);

            are[0] = fmaf(hre.x, wre, fmaf(-him.x, wim, are[0]));
            aim[0] = fmaf(hre.x, wim, fmaf( him.x, wre, aim[0]));
            are[1] = fmaf(hre.y, wre, fmaf(-him.y, wim, are[1]));
            aim[1] = fmaf(hre.y, wim, fmaf( him.y, wre, aim[1]));
            are[2] = fmaf(hre.z, wre, fmaf(-him.z, wim, are[2]));
            aim[2] = fmaf(hre.z, wim, fmaf( him.z, wre, aim[2]));
            are[3] = fmaf(hre.w, wre, fmaf(-him.w, wim, are[3]));
            aim[3] = fmaf(hre.w, wim, fmaf( him.w, wre, aim[3]));
        }

#pragma unroll
        for (int j = 0; j < 4; j++) {
            const int kidx = k0 + g * 4 + j;
            d_gp_re[mc * (KU * NU) + kidx * NU + n] = are[j];
            d_gp_im[mc * (KU * NU) + kidx * NU + n] = aim[j];
        }
    }
}

// ---------------------------------------------------------------------------
// k3: 512 blocks (4 p-groups x 128 k) x 128 threads.
// Phase 1: block (pg,k) sums its 8 partials per n -> d_gs[pg][k][n].
// Phase 2 (4th finisher per k): reduce 4 sums -> mag -> rowsum -> R[k].
// Phase 3 (128th k-finisher): deterministic global sum -> out; reset counters.
// ---------------------------------------------------------------------------
__global__ __launch_bounds__(128) void k3_rate(float* __restrict__ out)
{
    const int pg = blockIdx.x;        // 0..3
    const int k  = blockIdx.y;        // 0..127
    const int n  = threadIdx.x;       // 0..127

    // ---- phase 1: sum 8 partials (independent L2 loads, MLP 8) ----
    float gre = 0.f, gim = 0.f;
#pragma unroll
    for (int j = 0; j < NMC / PG; j++) {
        const int p = pg * (NMC / PG) + j;
        gre += d_gp_re[p * (KU * NU) + k * NU + n];
        gim += d_gp_im[p * (KU * NU) + k * NU + n];
    }
    d_gs_re[pg * (KU * NU) + k * NU + n] = gre;
    d_gs_im[pg * (KU * NU) + k * NU + n] = gim;

    __shared__ unsigned int flag_s;
    __shared__ float red[128];
    __shared__ float sig_s;

    __syncthreads();
    if (n == 0) {
        __threadfence();
        flag_s = (atomicAdd(&d_kctr[k], 1u) == PG - 1) ? 1u : 0u;
    }
    __syncthreads();
    if (!flag_s) return;
    __threadfence();   // acquire: other pg blocks' d_gs now visible

    // ---- phase 2: combine 4 p-group sums -> mag -> rowsum -> R[k] ----
    {
        float sre = (d_gs_re[0 * (KU * NU) + k * NU + n] + d_gs_re[1 * (KU * NU) + k * NU + n])
                  + (d_gs_re[2 * (KU * NU) + k * NU + n] + d_gs_re[3 * (KU * NU) + k * NU + n]);
        float sim = (d_gs_im[0 * (KU * NU) + k * NU + n] + d_gs_im[1 * (KU * NU) + k * NU + n])
                  + (d_gs_im[2 * (KU * NU) + k * NU + n] + d_gs_im[3 * (KU * NU) + k * NU + n]);
        const float mag = sqrtf(sre * sre + sim * sim);
        red[n] = mag;
        if (n == k) sig_s = mag;
    }
    __syncthreads();
#pragma unroll
    for (int s = 64; s > 0; s >>= 1) {
        if (n < s) red[n] += red[n + s];
        __syncthreads();
    }
    if (n == 0) {
        const float sig = sig_s;
        d_R[k] = sig / (red[0] - sig + N0F);
        __threadfence();
        flag_s = (atomicAdd(&d_ctr, 1u) == KU - 1) ? 1u : 0u;
    }
    __syncthreads();
    if (!flag_s) return;
    __threadfence();

    // ---- phase 3: global sum + output + counter reset ----
    red[n] = d_R[n];
    __syncthreads();
#pragma unroll
    for (int s = 64; s > 0; s >>= 1) {
        if (n < s) red[n] += red[n + s];
        __syncthreads();
    }
    if (n == 0) {
        out[0] = -red[0] * 1e6f;
        d_ctr = 0;
    }
    d_kctr[n] = 0;   // 128 threads reset 128 per-k counters
}

// ---------------------------------------------------------------------------
extern "C" void kernel_launch(void* const* d_in, const int* in_sizes, int n_in,
                              void* d_out, int out_size)
{
    const float* Wv  = (const float*)d_in[0];  // (1025, 256)
    const float* Ar  = (const float*)d_in[1];  // (128, 1024, 128)
    const float* Ai  = (const float*)d_in[2];
    const float* hdr = (const float*)d_in[3];  // (128, 1024)
    const float* hdi = (const float*)d_in[4];

    k12_fused<<<dim3(NMC, NKT), 256>>>(Wv, Ar, Ai, hdr, hdi);
    k3_rate<<<dim3(PG, KU), 128>>>((float*)d_out);
}